// round 5
// baseline (speedup 1.0000x reference)
#include <cuda_runtime.h>
#include <cuda_bf16.h>
#include <cstdint>

#define Bv 8
#define Av 1024
#define NNv 64
#define Gv 25
#define Fv 128
#define Lv 3
#define NBT 2048            // big-tiles: 4 atoms / 256 edges each
#define EDGE_GRID 152

#define WIDTHc (5.0f/24.0f)
#define COEFFc (-0.5f/(WIDTHc*WIDTHc))
#define LN2c 0.6931471805599453f

// ---- dynamic smem offsets (bytes) for edge kernel ----
#define OFF_YT   0          // bf16 [256 e][136]  stride 272B   (69632 B)
#define OFF_FW2T 69632      // bf16 [128 f][152]  stride 304B   (38912 B)
#define OFF_FB1  108544     // f32 [128]
#define OFF_SR   109056     // f32 [256]
#define OFF_SM   110080     // f32 [256]
#define OFF_VSM  111104     // f32 [8][128]
#define OFF_FW1P 115200     // uint2 [2s][16n][32lane]          (16384 B)
#define SMEM_EDGE 131584

// ---------------- scratch ----------------
__device__ __nv_bfloat16 g_y[Bv*Av*Fv];
__device__ float g_v[Bv*Av*Fv];
__device__ float g_r[Bv*Av*NNv];

// ---------------- helpers ----------------
__device__ __forceinline__ float ssp(float x) {
    // softplus(x)-ln2, 1 MUFU: u=e^{-|x|}, ln(1+u) via A&S 4.1.43 poly
    float u = __expf(-fabsf(x));
    float p = u*(0.99949556f + u*(-0.49190896f + u*(0.28947478f
              + u*(-0.13606275f + u*0.03215845f))));
    return fmaxf(x, 0.0f) + p - LN2c;
}
__device__ __forceinline__ uint32_t s2u(const void* p) {
    uint32_t a;
    asm("{ .reg .u64 t; cvta.to.shared.u64 t, %1; cvt.u32.u64 %0, t; }" : "=r"(a) : "l"(p));
    return a;
}
__device__ __forceinline__ uint32_t bf16pk(float lo, float hi) {
    uint32_t r;
    asm("cvt.rn.bf16x2.f32 %0, %1, %2;" : "=r"(r) : "f"(hi), "f"(lo));
    return r;
}
__device__ __forceinline__ float2 bf2f(uint32_t p) {
    float2 r;
    r.x = __uint_as_float(p << 16);
    r.y = __uint_as_float(p & 0xffff0000u);
    return r;
}
__device__ __forceinline__ void mma_bf16(float* d, const uint32_t* a, const uint32_t* b) {
    asm volatile(
        "mma.sync.aligned.m16n8k16.row.col.f32.bf16.bf16.f32 "
        "{%0,%1,%2,%3}, {%4,%5,%6,%7}, {%8,%9}, {%0,%1,%2,%3};"
        : "+f"(d[0]), "+f"(d[1]), "+f"(d[2]), "+f"(d[3])
        : "r"(a[0]), "r"(a[1]), "r"(a[2]), "r"(a[3]), "r"(b[0]), "r"(b[1]));
}
__device__ __forceinline__ void cp16(uint32_t dst, const void* src) {
    asm volatile("cp.async.ca.shared.global [%0], [%1], 16;" :: "r"(dst), "l"(src) : "memory");
}
__device__ __forceinline__ unsigned long long fma2(unsigned long long a,
                                                   unsigned long long b,
                                                   unsigned long long c) {
    unsigned long long d;
    asm("fma.rn.f32x2 %0, %1, %2, %3;" : "=l"(d) : "l"(a), "l"(b), "l"(c));
    return d;
}
__device__ __forceinline__ unsigned long long pack2(float lo, float hi) {
    unsigned long long d;
    asm("mov.b64 %0, {%1, %2};" : "=l"(d) : "f"(lo), "f"(hi));
    return d;
}
__device__ __forceinline__ float hsum2(unsigned long long v) {
    float lo, hi;
    asm("mov.b64 {%0, %1}, %2;" : "=f"(lo), "=f"(hi) : "l"(v));
    return lo + hi;
}

// 64-row x 128x128 GEMM core: thread owns column f, rows [r0, r0+32).
// sbuf: smem [64][128] f32 row-major. W: global [128 k][128 f].
// Packed f32x2: even/odd-k accumulators per row.
__device__ __forceinline__ void gemm_block(const float* sbuf, const float* __restrict__ W,
                                           int f, int r0, float* out)
{
    unsigned long long acc[32];
    #pragma unroll
    for (int i = 0; i < 32; ++i) acc[i] = 0ull;
    const unsigned long long* xs = (const unsigned long long*)sbuf;
    #pragma unroll 2
    for (int kp = 0; kp < 64; ++kp) {
        unsigned long long wp = pack2(__ldg(W + 2*kp*Fv + f), __ldg(W + (2*kp+1)*Fv + f));
        #pragma unroll
        for (int r = 0; r < 32; ++r)
            acc[r] = fma2(xs[(r0 + r)*64 + kp], wp, acc[r]);
    }
    #pragma unroll
    for (int r = 0; r < 32; ++r) out[r] = hsum2(acc[r]);
}

// ---------------- kernel 0: embedding + distances + y0 GEMM ----------------
__global__ __launch_bounds__(256)
void init_y_kernel(const int* __restrict__ zA, const float* __restrict__ pos,
                   const float* __restrict__ cell, const float* __restrict__ off,
                   const int* __restrict__ nbr, const float* __restrict__ emb,
                   const float* __restrict__ W3, float* __restrict__ x)
{
    __shared__ float bufA[64*Fv];
    __shared__ int zs[64];
    const int t = threadIdx.x;
    const int f = t & 127, q = t >> 7;
    const int row0 = blockIdx.x * 64;
    const int r0 = q * 32;

    if (t < 64) zs[t] = zA[row0 + t];

    // distances for this block's 64 atoms x 64 neighbors
    for (int i = t; i < 64*NNv; i += 256) {
        int atom = row0 + (i >> 6);
        int e = atom*NNv + (i & 63);
        int b = atom >> 10;
        int nb = nbr[e];
        const float* pi = pos + (size_t)atom*3;
        const float* pj = pos + (size_t)((b<<10) + nb)*3;
        const float* o  = off + (size_t)e*3;
        const float* c  = cell + b*9;
        float dx = pj[0]-pi[0] + o[0]*c[0] + o[1]*c[3] + o[2]*c[6];
        float dy = pj[1]-pi[1] + o[0]*c[1] + o[1]*c[4] + o[2]*c[7];
        float dz = pj[2]-pi[2] + o[0]*c[2] + o[1]*c[5] + o[2]*c[8];
        float d2 = dx*dx + dy*dy + dz*dz;
        g_r[e] = (d2 > 0.0f) ? sqrtf(d2) : 0.0f;
    }
    __syncthreads();

    #pragma unroll
    for (int r = 0; r < 32; ++r) {
        int row = r0 + r;
        float val = emb[(size_t)zs[row]*Fv + f];
        bufA[row*Fv + f] = val;
        x[(size_t)(row0 + row)*Fv + f] = val;
    }
    __syncthreads();

    float out[32];
    gemm_block(bufA, W3, f, r0, out);
    #pragma unroll
    for (int r = 0; r < 32; ++r)
        g_y[(size_t)(row0 + r0 + r)*Fv + f] = __float2bfloat16(out[r]);
}

// ---------------- kernel 2: mma.sync fused filter-net + cfconv ----------------
__global__ __launch_bounds__(256, 1)
void edge_mma_kernel(const float* __restrict__ fw1, const float* __restrict__ fb1,
                     const float* __restrict__ fw2, const float* __restrict__ fb2,
                     const int* __restrict__ nbr, const float* __restrict__ msk)
{
    extern __shared__ __align__(16) char sm[];
    __nv_bfloat16* YT   = (__nv_bfloat16*)(sm + OFF_YT);     // [256][136]
    __nv_bfloat16* FW2T = (__nv_bfloat16*)(sm + OFF_FW2T);   // [128][152]
    float* FB1 = (float*)(sm + OFF_FB1);
    float* SR  = (float*)(sm + OFF_SR);
    float* SMk = (float*)(sm + OFF_SM);
    float* VSM = (float*)(sm + OFF_VSM);
    uint2* FW1P = (uint2*)(sm + OFF_FW1P);                   // [2s*16n][32 lane]

    const int t    = threadIdx.x;
    const int w    = t >> 5;
    const int lane = t & 31;
    const int qr   = lane >> 2;   // 0..7
    const int qc   = lane & 3;    // 0..3
    const uint32_t yt_base = s2u(YT);

    // ---- per-layer setup ----
    if (t < 128) FB1[t] = fb1[t];
    {   // fw2^T -> smem [f][k], virtual col 128 = fb2, 129..151 = 0
        const int f = t >> 1;
        const int k0 = (t & 1) * 64;
        for (int k = 0; k < 64; ++k)
            FW2T[f*152 + k0 + k] = __float2bfloat16(fw2[(k0 + k)*Fv + f]);
        if (t & 1) {
            FW2T[f*152 + 128] = __float2bfloat16(fb2[f]);
            for (int k = 129; k < 152; ++k) FW2T[f*152 + k] = __float2bfloat16(0.0f);
        }
    }
    // fw1 B-fragments -> smem (identical for all warps; warp 0 fills)
    if (t < 32) {
        #pragma unroll
        for (int s = 0; s < 2; ++s) {
            #pragma unroll
            for (int n = 0; n < 16; ++n) {
                int g = 2*qc + 16*s;
                int fn = 8*n + qr;
                float w00 = (g   < Gv) ? fw1[(g  )*Fv + fn] : 0.0f;
                float w01 = (g+1 < Gv) ? fw1[(g+1)*Fv + fn] : 0.0f;
                float w10 = (g+8 < Gv) ? fw1[(g+8)*Fv + fn] : 0.0f;
                float w11 = (g+9 < Gv) ? fw1[(g+9)*Fv + fn] : 0.0f;
                FW1P[(s*16 + n)*32 + lane] = make_uint2(bf16pk(w00, w01), bf16pk(w10, w11));
            }
        }
    }
    __syncthreads();

    for (int bt = blockIdx.x; bt < NBT; bt += gridDim.x) {
        const int e0 = bt * 256;
        // ---- stage y rows (bf16) via cp.async; one row per thread ----
        {
            int nb = __ldg(nbr + e0 + t);
            int batch = (e0 + t) >> 16;
            const __nv_bfloat16* src = g_y + ((size_t)batch << 17) + (size_t)nb * Fv;
            uint32_t dst = yt_base + (uint32_t)t * 272u;
            #pragma unroll
            for (int j = 0; j < 8; ++j)
                cp16(dst + 16u*j, (const char*)src + 16*j);
            asm volatile("cp.async.commit_group;" ::: "memory");
            #pragma unroll
            for (int j = 8; j < 16; ++j)
                cp16(dst + 16u*j, (const char*)src + 16*j);
            asm volatile("cp.async.commit_group;" ::: "memory");
            SR[t]  = g_r[e0 + t];
            SMk[t] = msk[e0 + t];
        }
        __syncthreads();

        // ---- GEMM1 -> A2 fragments (registers only) ----
        uint32_t A2[2][9][4];
        #pragma unroll
        for (int Mt = 0; Mt < 2; ++Mt) {
            const int r0 = 32*w + 16*Mt + qr;
            const int r1 = r0 + 8;
            const float rr0 = SR[r0], rr1 = SR[r1];
            const float m0 = SMk[r0], m1 = SMk[r1];

            uint32_t Af[2][4];
            #pragma unroll
            for (int s = 0; s < 2; ++s) {
                const int g = 2*qc + 16*s;
                float d, e00, e01, e02, e03, e10, e11, e12, e13;
                d = rr0 - (g  )*WIDTHc; e00 = (g   < Gv) ? __expf(COEFFc*d*d) : 0.0f;
                d = rr0 - (g+1)*WIDTHc; e01 = (g+1 < Gv) ? __expf(COEFFc*d*d) : 0.0f;
                d = rr0 - (g+8)*WIDTHc; e02 = (g+8 < Gv) ? __expf(COEFFc*d*d) : 0.0f;
                d = rr0 - (g+9)*WIDTHc; e03 = (g+9 < Gv) ? __expf(COEFFc*d*d) : 0.0f;
                d = rr1 - (g  )*WIDTHc; e10 = (g   < Gv) ? __expf(COEFFc*d*d) : 0.0f;
                d = rr1 - (g+1)*WIDTHc; e11 = (g+1 < Gv) ? __expf(COEFFc*d*d) : 0.0f;
                d = rr1 - (g+8)*WIDTHc; e12 = (g+8 < Gv) ? __expf(COEFFc*d*d) : 0.0f;
                d = rr1 - (g+9)*WIDTHc; e13 = (g+9 < Gv) ? __expf(COEFFc*d*d) : 0.0f;
                Af[s][0] = bf16pk(e00, e01);
                Af[s][1] = bf16pk(e10, e11);
                Af[s][2] = bf16pk(e02, e03);
                Af[s][3] = bf16pk(e12, e13);
            }

            #pragma unroll
            for (int s2 = 0; s2 < 8; ++s2) {
                #pragma unroll
                for (int nn = 0; nn < 2; ++nn) {
                    const int n = 2*s2 + nn;
                    float acc[4] = {0.0f, 0.0f, 0.0f, 0.0f};
                    uint2 u0 = FW1P[n*32 + lane];
                    uint2 u1 = FW1P[(16 + n)*32 + lane];
                    uint32_t bb0[2] = {u0.x, u0.y};
                    uint32_t bb1[2] = {u1.x, u1.y};
                    mma_bf16(acc, Af[0], bb0);
                    mma_bf16(acc, Af[1], bb1);
                    float bA = FB1[8*n + 2*qc];
                    float bB = FB1[8*n + 2*qc + 1];
                    float h0 = ssp(acc[0] + bA) * m0;
                    float h1 = ssp(acc[1] + bB) * m0;
                    float h2 = ssp(acc[2] + bA) * m1;
                    float h3 = ssp(acc[3] + bB) * m1;
                    A2[Mt][s2][2*nn    ] = bf16pk(h0, h1);
                    A2[Mt][s2][2*nn + 1] = bf16pk(h2, h3);
                }
            }
            A2[Mt][8][0] = (qc == 0) ? bf16pk(m0, 0.0f) : 0u;
            A2[Mt][8][1] = (qc == 0) ? bf16pk(m1, 0.0f) : 0u;
            A2[Mt][8][2] = 0u;
            A2[Mt][8][3] = 0u;
        }

        asm volatile("cp.async.wait_group 0;" ::: "memory");
        __syncthreads();

        // ---- GEMM2 + epilogue over 4 f-chunks of 32 ----
        #pragma unroll
        for (int ch = 0; ch < 4; ++ch) {
            float acc2[2][4][4];
            #pragma unroll
            for (int Mt = 0; Mt < 2; ++Mt)
                #pragma unroll
                for (int n = 0; n < 4; ++n)
                    #pragma unroll
                    for (int i = 0; i < 4; ++i) acc2[Mt][n][i] = 0.0f;

            #pragma unroll
            for (int s = 0; s < 9; ++s) {
                #pragma unroll
                for (int n = 0; n < 4; ++n) {
                    int fB = 32*ch + 8*n + qr;
                    int k0 = 16*s + 2*qc;
                    uint32_t bb[2];
                    bb[0] = *(const uint32_t*)(FW2T + fB*152 + k0);
                    bb[1] = *(const uint32_t*)(FW2T + fB*152 + k0 + 8);
                    mma_bf16(acc2[0][n], A2[0][s], bb);
                    mma_bf16(acc2[1][n], A2[1][s], bb);
                }
            }

            float vp[8];
            #pragma unroll
            for (int i = 0; i < 8; ++i) vp[i] = 0.0f;
            #pragma unroll
            for (int Mt = 0; Mt < 2; ++Mt) {
                const int rl = 32*w + 16*Mt + qr;
                #pragma unroll
                for (int n = 0; n < 4; ++n) {
                    int fc = 32*ch + 8*n + 2*qc;
                    uint32_t y0 = *(const uint32_t*)(YT + rl*136 + fc);
                    uint32_t y1 = *(const uint32_t*)(YT + (rl+8)*136 + fc);
                    float2 f0 = bf2f(y0);
                    float2 f1 = bf2f(y1);
                    vp[2*n]   = fmaf(acc2[Mt][n][0], f0.x, fmaf(acc2[Mt][n][2], f1.x, vp[2*n]));
                    vp[2*n+1] = fmaf(acc2[Mt][n][1], f0.y, fmaf(acc2[Mt][n][3], f1.y, vp[2*n+1]));
                }
            }
            #pragma unroll
            for (int i = 0; i < 8; ++i) {
                vp[i] += __shfl_xor_sync(0xffffffffu, vp[i], 4);
                vp[i] += __shfl_xor_sync(0xffffffffu, vp[i], 8);
                vp[i] += __shfl_xor_sync(0xffffffffu, vp[i], 16);
            }
            if (lane < 4) {
                #pragma unroll
                for (int n = 0; n < 4; ++n) {
                    VSM[w*128 + 32*ch + 8*n + 2*lane    ] = vp[2*n];
                    VSM[w*128 + 32*ch + 8*n + 2*lane + 1] = vp[2*n+1];
                }
            }
        }
        __syncthreads();

        // ---- combine warp pairs -> g_v ----
        {
            int f = t & 127;
            int a0 = t >> 7;
            #pragma unroll
            for (int a = 0; a < 2; ++a) {
                int atom = a0 + 2*a;
                g_v[(size_t)(4*bt + atom)*Fv + f] =
                    VSM[(2*atom)*128 + f] + VSM[(2*atom+1)*128 + f];
            }
        }
        __syncthreads();
    }
}

// ---------------- kernel 3: x += dense(ssp(f2out(v)))  [+ next-layer in2f] ----------------
template<int DO_Y>
__global__ __launch_bounds__(256)
void fused_post(const float* __restrict__ W1, const float* __restrict__ B1,
                const float* __restrict__ W2, const float* __restrict__ B2,
                const float* __restrict__ W3, float* __restrict__ x)
{
    extern __shared__ float fsm[];
    float* bufA = fsm;              // [64][128]
    float* bufB = fsm + 64*Fv;      // [64][128]
    const int t = threadIdx.x;
    const int f = t & 127, q = t >> 7;
    const int row0 = blockIdx.x * 64;
    const int r0 = q * 32;

    {   // load v tile
        const float4* src = (const float4*)(g_v + (size_t)row0 * Fv);
        float4* dst = (float4*)bufA;
        #pragma unroll
        for (int i = 0; i < 8; ++i) dst[t + 256*i] = src[t + 256*i];
    }
    __syncthreads();

    float out[32];
    gemm_block(bufA, W1, f, r0, out);
    {
        float b = __ldg(B1 + f);
        #pragma unroll
        for (int r = 0; r < 32; ++r)
            bufB[(r0 + r)*Fv + f] = ssp(out[r] + b);
    }
    __syncthreads();

    gemm_block(bufB, W2, f, r0, out);
    {
        float b = __ldg(B2 + f);
        #pragma unroll
        for (int r = 0; r < 32; ++r) {
            size_t gi = (size_t)(row0 + r0 + r)*Fv + f;
            float xn = x[gi] + out[r] + b;
            x[gi] = xn;
            if (DO_Y) bufA[(r0 + r)*Fv + f] = xn;
        }
    }
    if (DO_Y) {
        __syncthreads();
        gemm_block(bufA, W3, f, r0, out);
        #pragma unroll
        for (int r = 0; r < 32; ++r)
            g_y[(size_t)(row0 + r0 + r)*Fv + f] = __float2bfloat16(out[r]);
    }
}

// ---------------- launcher ----------------
extern "C" void kernel_launch(void* const* d_in, const int* in_sizes, int n_in,
                              void* d_out, int out_size)
{
    const int*   zA   = (const int*)  d_in[0];
    const float* pos  = (const float*)d_in[1];
    const float* cell = (const float*)d_in[2];
    const float* off  = (const float*)d_in[3];
    const int*   nbr  = (const int*)  d_in[4];
    const float* msk  = (const float*)d_in[5];
    const float* emb  = (const float*)d_in[6];
    const float* fw1  = (const float*)d_in[7];
    const float* fb1  = (const float*)d_in[8];
    const float* fw2  = (const float*)d_in[9];
    const float* fb2  = (const float*)d_in[10];
    const float* i2f  = (const float*)d_in[11];
    const float* f2o  = (const float*)d_in[12];
    const float* f2ob = (const float*)d_in[13];
    const float* dw   = (const float*)d_in[14];
    const float* db   = (const float*)d_in[15];
    float* x = (float*)d_out;

    cudaFuncSetAttribute(edge_mma_kernel,
                         cudaFuncAttributeMaxDynamicSharedMemorySize, SMEM_EDGE);
    cudaFuncSetAttribute(fused_post<1>,
                         cudaFuncAttributeMaxDynamicSharedMemorySize, 65536);
    cudaFuncSetAttribute(fused_post<0>,
                         cudaFuncAttributeMaxDynamicSharedMemorySize, 65536);

    init_y_kernel<<<(Bv*Av)/64, 256>>>(zA, pos, cell, off, nbr, emb, i2f, x);
    for (int l = 0; l < Lv; ++l) {
        edge_mma_kernel<<<EDGE_GRID, 256, SMEM_EDGE>>>(
            fw1 + (size_t)l*Gv*Fv, fb1 + (size_t)l*Fv,
            fw2 + (size_t)l*Fv*Fv, fb2 + (size_t)l*Fv, nbr, msk);
        if (l < Lv - 1)
            fused_post<1><<<(Bv*Av)/64, 256, 65536>>>(
                f2o + (size_t)l*Fv*Fv, f2ob + (size_t)l*Fv,
                dw  + (size_t)l*Fv*Fv, db   + (size_t)l*Fv,
                i2f + (size_t)(l+1)*Fv*Fv, x);
        else
            fused_post<0><<<(Bv*Av)/64, 256, 65536>>>(
                f2o + (size_t)l*Fv*Fv, f2ob + (size_t)l*Fv,
                dw  + (size_t)l*Fv*Fv, db   + (size_t)l*Fv,
                (const float*)nullptr, x);
    }
}

// round 6
// speedup vs baseline: 1.0706x; 1.0706x over previous
#include <cuda_runtime.h>
#include <cuda_bf16.h>
#include <cstdint>

#define Bv 8
#define Av 1024
#define NNv 64
#define Gv 25
#define Fv 128
#define Lv 3
#define NBT 4096            // tiles: 2 atoms / 128 edges each
#define EDGE_GRID 304

#define WIDTHc (5.0f/24.0f)
#define COEFFc (-0.5f/(WIDTHc*WIDTHc))
#define LN2c 0.6931471805599453f

// ---- dynamic smem offsets (bytes) for edge kernel (128-thr CTA) ----
#define OFF_YT   0          // bf16 [128 e][136]  stride 272B  (34816 B)
#define OFF_FW2T 34816      // bf16 [128 f][152]  stride 304B  (38912 B)
#define OFF_FB1  73728      // f32 [128]
#define OFF_SR   74240      // f32 [128]
#define OFF_SM   74752      // f32 [128]
#define OFF_VSM  75264      // f32 [4][128]
#define SMEM_EDGE 77312

// ---------------- scratch ----------------
__device__ __nv_bfloat16 g_y[Bv*Av*Fv];
__device__ float g_v[Bv*Av*Fv];
__device__ float g_r[Bv*Av*NNv];

// ---------------- helpers ----------------
__device__ __forceinline__ float ssp(float x) {
    // softplus(x)-ln2, 1 MUFU: u=e^{-|x|}, ln(1+u) via A&S 4.1.43 poly
    float u = __expf(-fabsf(x));
    float p = u*(0.99949556f + u*(-0.49190896f + u*(0.28947478f
              + u*(-0.13606275f + u*0.03215845f))));
    return fmaxf(x, 0.0f) + p - LN2c;
}
__device__ __forceinline__ uint32_t s2u(const void* p) {
    uint32_t a;
    asm("{ .reg .u64 t; cvta.to.shared.u64 t, %1; cvt.u32.u64 %0, t; }" : "=r"(a) : "l"(p));
    return a;
}
__device__ __forceinline__ uint32_t bf16pk(float lo, float hi) {
    uint32_t r;
    asm("cvt.rn.bf16x2.f32 %0, %1, %2;" : "=r"(r) : "f"(hi), "f"(lo));
    return r;
}
__device__ __forceinline__ float2 bf2f(uint32_t p) {
    float2 r;
    r.x = __uint_as_float(p << 16);
    r.y = __uint_as_float(p & 0xffff0000u);
    return r;
}
__device__ __forceinline__ void mma_bf16(float* d, const uint32_t* a, const uint32_t* b) {
    asm volatile(
        "mma.sync.aligned.m16n8k16.row.col.f32.bf16.bf16.f32 "
        "{%0,%1,%2,%3}, {%4,%5,%6,%7}, {%8,%9}, {%0,%1,%2,%3};"
        : "+f"(d[0]), "+f"(d[1]), "+f"(d[2]), "+f"(d[3])
        : "r"(a[0]), "r"(a[1]), "r"(a[2]), "r"(a[3]), "r"(b[0]), "r"(b[1]));
}
__device__ __forceinline__ void cp16(uint32_t dst, const void* src) {
    asm volatile("cp.async.ca.shared.global [%0], [%1], 16;" :: "r"(dst), "l"(src) : "memory");
}
__device__ __forceinline__ unsigned long long fma2(unsigned long long a,
                                                   unsigned long long b,
                                                   unsigned long long c) {
    unsigned long long d;
    asm("fma.rn.f32x2 %0, %1, %2, %3;" : "=l"(d) : "l"(a), "l"(b), "l"(c));
    return d;
}
__device__ __forceinline__ unsigned long long pack2(float lo, float hi) {
    unsigned long long d;
    asm("mov.b64 %0, {%1, %2};" : "=l"(d) : "f"(lo), "f"(hi));
    return d;
}
__device__ __forceinline__ float hsum2(unsigned long long v) {
    float lo, hi;
    asm("mov.b64 {%0, %1}, %2;" : "=f"(lo), "=f"(hi) : "l"(v));
    return lo + hi;
}

// 64-row x 128x128 GEMM core: thread owns column f, rows [r0, r0+32).
__device__ __forceinline__ void gemm_block(const float* sbuf, const float* __restrict__ W,
                                           int f, int r0, float* out)
{
    unsigned long long acc[32];
    #pragma unroll
    for (int i = 0; i < 32; ++i) acc[i] = 0ull;
    const unsigned long long* xs = (const unsigned long long*)sbuf;
    #pragma unroll 2
    for (int kp = 0; kp < 64; ++kp) {
        unsigned long long wp = pack2(__ldg(W + 2*kp*Fv + f), __ldg(W + (2*kp+1)*Fv + f));
        #pragma unroll
        for (int r = 0; r < 32; ++r)
            acc[r] = fma2(xs[(r0 + r)*64 + kp], wp, acc[r]);
    }
    #pragma unroll
    for (int r = 0; r < 32; ++r) out[r] = hsum2(acc[r]);
}

// ---------------- kernel 0: embedding + distances + y0 GEMM ----------------
__global__ __launch_bounds__(256)
void init_y_kernel(const int* __restrict__ zA, const float* __restrict__ pos,
                   const float* __restrict__ cell, const float* __restrict__ off,
                   const int* __restrict__ nbr, const float* __restrict__ emb,
                   const float* __restrict__ W3, float* __restrict__ x)
{
    __shared__ float bufA[64*Fv];
    __shared__ int zs[64];
    const int t = threadIdx.x;
    const int f = t & 127, q = t >> 7;
    const int row0 = blockIdx.x * 64;
    const int r0 = q * 32;

    if (t < 64) zs[t] = zA[row0 + t];

    for (int i = t; i < 64*NNv; i += 256) {
        int atom = row0 + (i >> 6);
        int e = atom*NNv + (i & 63);
        int b = atom >> 10;
        int nb = nbr[e];
        const float* pi = pos + (size_t)atom*3;
        const float* pj = pos + (size_t)((b<<10) + nb)*3;
        const float* o  = off + (size_t)e*3;
        const float* c  = cell + b*9;
        float dx = pj[0]-pi[0] + o[0]*c[0] + o[1]*c[3] + o[2]*c[6];
        float dy = pj[1]-pi[1] + o[0]*c[1] + o[1]*c[4] + o[2]*c[7];
        float dz = pj[2]-pi[2] + o[0]*c[2] + o[1]*c[5] + o[2]*c[8];
        float d2 = dx*dx + dy*dy + dz*dz;
        g_r[e] = (d2 > 0.0f) ? sqrtf(d2) : 0.0f;
    }
    __syncthreads();

    #pragma unroll
    for (int r = 0; r < 32; ++r) {
        int row = r0 + r;
        float val = emb[(size_t)zs[row]*Fv + f];
        bufA[row*Fv + f] = val;
        x[(size_t)(row0 + row)*Fv + f] = val;
    }
    __syncthreads();

    float out[32];
    gemm_block(bufA, W3, f, r0, out);
    #pragma unroll
    for (int r = 0; r < 32; ++r)
        g_y[(size_t)(row0 + r0 + r)*Fv + f] = __float2bfloat16(out[r]);
}

// ---------------- kernel 2: mma.sync fused filter-net + cfconv ----------------
// 128-thr CTA = 2 atoms = 128 edges; 2 CTAs/SM for barrier overlap.
// Warp w owns edges [32w, 32w+32) (2 M-tiles). fw1 B-frags in registers.
__global__ __launch_bounds__(128)
void edge_mma_kernel(const float* __restrict__ fw1, const float* __restrict__ fb1,
                     const float* __restrict__ fw2, const float* __restrict__ fb2,
                     const int* __restrict__ nbr, const float* __restrict__ msk)
{
    extern __shared__ __align__(16) char sm[];
    __nv_bfloat16* YT   = (__nv_bfloat16*)(sm + OFF_YT);     // [128][136]
    __nv_bfloat16* FW2T = (__nv_bfloat16*)(sm + OFF_FW2T);   // [128][152]
    float* FB1 = (float*)(sm + OFF_FB1);
    float* SR  = (float*)(sm + OFF_SR);
    float* SMk = (float*)(sm + OFF_SM);
    float* VSM = (float*)(sm + OFF_VSM);

    const int t    = threadIdx.x;
    const int w    = t >> 5;
    const int lane = t & 31;
    const int qr   = lane >> 2;   // 0..7
    const int qc   = lane & 3;    // 0..3
    const uint32_t yt_base = s2u(YT);

    // ---- per-layer setup ----
    FB1[t] = fb1[t];
    {   // fw2^T -> smem [f][k], virtual col 128 = fb2, 129..151 = 0
        const int f = t;
        for (int k = 0; k < 128; ++k)
            FW2T[f*152 + k] = __float2bfloat16(fw2[k*Fv + f]);
        FW2T[f*152 + 128] = __float2bfloat16(fb2[f]);
        for (int k = 129; k < 152; ++k) FW2T[f*152 + k] = __float2bfloat16(0.0f);
    }
    // fw1 B-fragments in registers: [kstep s][ntile n][2]
    uint32_t b1f[2][16][2];
    #pragma unroll
    for (int s = 0; s < 2; ++s) {
        #pragma unroll
        for (int n = 0; n < 16; ++n) {
            int g = 2*qc + 16*s;
            int fn = 8*n + qr;
            float w00 = (g   < Gv) ? fw1[(g  )*Fv + fn] : 0.0f;
            float w01 = (g+1 < Gv) ? fw1[(g+1)*Fv + fn] : 0.0f;
            float w10 = (g+8 < Gv) ? fw1[(g+8)*Fv + fn] : 0.0f;
            float w11 = (g+9 < Gv) ? fw1[(g+9)*Fv + fn] : 0.0f;
            b1f[s][n][0] = bf16pk(w00, w01);
            b1f[s][n][1] = bf16pk(w10, w11);
        }
    }
    __syncthreads();

    for (int bt = blockIdx.x; bt < NBT; bt += gridDim.x) {
        const int e0 = bt * 128;
        // ---- stage y rows (bf16) via cp.async; one row per thread ----
        {
            int nb = __ldg(nbr + e0 + t);
            int batch = (e0 + t) >> 16;
            const __nv_bfloat16* src = g_y + ((size_t)batch << 17) + (size_t)nb * Fv;
            uint32_t dst = yt_base + (uint32_t)t * 272u;
            #pragma unroll
            for (int j = 0; j < 8; ++j)
                cp16(dst + 16u*j, (const char*)src + 16*j);
            asm volatile("cp.async.commit_group;" ::: "memory");
            #pragma unroll
            for (int j = 8; j < 16; ++j)
                cp16(dst + 16u*j, (const char*)src + 16*j);
            asm volatile("cp.async.commit_group;" ::: "memory");
            SR[t]  = g_r[e0 + t];
            SMk[t] = msk[e0 + t];
        }
        __syncthreads();

        // ---- GEMM1 -> A2 fragments (registers only) ----
        uint32_t A2[2][9][4];
        #pragma unroll
        for (int Mt = 0; Mt < 2; ++Mt) {
            const int r0 = 32*w + 16*Mt + qr;
            const int r1 = r0 + 8;
            const float rr0 = SR[r0], rr1 = SR[r1];
            const float m0 = SMk[r0], m1 = SMk[r1];

            uint32_t Af[2][4];
            #pragma unroll
            for (int s = 0; s < 2; ++s) {
                const int g = 2*qc + 16*s;
                float d, e00, e01, e02, e03, e10, e11, e12, e13;
                d = rr0 - (g  )*WIDTHc; e00 = (g   < Gv) ? __expf(COEFFc*d*d) : 0.0f;
                d = rr0 - (g+1)*WIDTHc; e01 = (g+1 < Gv) ? __expf(COEFFc*d*d) : 0.0f;
                d = rr0 - (g+8)*WIDTHc; e02 = (g+8 < Gv) ? __expf(COEFFc*d*d) : 0.0f;
                d = rr0 - (g+9)*WIDTHc; e03 = (g+9 < Gv) ? __expf(COEFFc*d*d) : 0.0f;
                d = rr1 - (g  )*WIDTHc; e10 = (g   < Gv) ? __expf(COEFFc*d*d) : 0.0f;
                d = rr1 - (g+1)*WIDTHc; e11 = (g+1 < Gv) ? __expf(COEFFc*d*d) : 0.0f;
                d = rr1 - (g+8)*WIDTHc; e12 = (g+8 < Gv) ? __expf(COEFFc*d*d) : 0.0f;
                d = rr1 - (g+9)*WIDTHc; e13 = (g+9 < Gv) ? __expf(COEFFc*d*d) : 0.0f;
                Af[s][0] = bf16pk(e00, e01);
                Af[s][1] = bf16pk(e10, e11);
                Af[s][2] = bf16pk(e02, e03);
                Af[s][3] = bf16pk(e12, e13);
            }

            #pragma unroll
            for (int s2 = 0; s2 < 8; ++s2) {
                #pragma unroll
                for (int nn = 0; nn < 2; ++nn) {
                    const int n = 2*s2 + nn;
                    float acc[4] = {0.0f, 0.0f, 0.0f, 0.0f};
                    mma_bf16(acc, Af[0], b1f[0][n]);
                    mma_bf16(acc, Af[1], b1f[1][n]);
                    float bA = FB1[8*n + 2*qc];
                    float bB = FB1[8*n + 2*qc + 1];
                    float h0 = ssp(acc[0] + bA) * m0;
                    float h1 = ssp(acc[1] + bB) * m0;
                    float h2 = ssp(acc[2] + bA) * m1;
                    float h3 = ssp(acc[3] + bB) * m1;
                    A2[Mt][s2][2*nn    ] = bf16pk(h0, h1);
                    A2[Mt][s2][2*nn + 1] = bf16pk(h2, h3);
                }
            }
            A2[Mt][8][0] = (qc == 0) ? bf16pk(m0, 0.0f) : 0u;
            A2[Mt][8][1] = (qc == 0) ? bf16pk(m1, 0.0f) : 0u;
            A2[Mt][8][2] = 0u;
            A2[Mt][8][3] = 0u;
        }

        asm volatile("cp.async.wait_group 0;" ::: "memory");
        __syncthreads();

        // ---- GEMM2 + epilogue over 4 f-chunks of 32 ----
        #pragma unroll
        for (int ch = 0; ch < 4; ++ch) {
            float acc2[2][4][4];
            #pragma unroll
            for (int Mt = 0; Mt < 2; ++Mt)
                #pragma unroll
                for (int n = 0; n < 4; ++n)
                    #pragma unroll
                    for (int i = 0; i < 4; ++i) acc2[Mt][n][i] = 0.0f;

            #pragma unroll
            for (int s = 0; s < 9; ++s) {
                #pragma unroll
                for (int n = 0; n < 4; ++n) {
                    int fB = 32*ch + 8*n + qr;
                    int k0 = 16*s + 2*qc;
                    uint32_t bb[2];
                    bb[0] = *(const uint32_t*)(FW2T + fB*152 + k0);
                    bb[1] = *(const uint32_t*)(FW2T + fB*152 + k0 + 8);
                    mma_bf16(acc2[0][n], A2[0][s], bb);
                    mma_bf16(acc2[1][n], A2[1][s], bb);
                }
            }

            float vp[8];
            #pragma unroll
            for (int i = 0; i < 8; ++i) vp[i] = 0.0f;
            #pragma unroll
            for (int Mt = 0; Mt < 2; ++Mt) {
                const int rl = 32*w + 16*Mt + qr;
                #pragma unroll
                for (int n = 0; n < 4; ++n) {
                    int fc = 32*ch + 8*n + 2*qc;
                    uint32_t y0 = *(const uint32_t*)(YT + rl*136 + fc);
                    uint32_t y1 = *(const uint32_t*)(YT + (rl+8)*136 + fc);
                    float2 f0 = bf2f(y0);
                    float2 f1 = bf2f(y1);
                    vp[2*n]   = fmaf(acc2[Mt][n][0], f0.x, fmaf(acc2[Mt][n][2], f1.x, vp[2*n]));
                    vp[2*n+1] = fmaf(acc2[Mt][n][1], f0.y, fmaf(acc2[Mt][n][3], f1.y, vp[2*n+1]));
                }
            }
            #pragma unroll
            for (int i = 0; i < 8; ++i) {
                vp[i] += __shfl_xor_sync(0xffffffffu, vp[i], 4);
                vp[i] += __shfl_xor_sync(0xffffffffu, vp[i], 8);
                vp[i] += __shfl_xor_sync(0xffffffffu, vp[i], 16);
            }
            if (lane < 4) {
                #pragma unroll
                for (int n = 0; n < 4; ++n) {
                    VSM[w*128 + 32*ch + 8*n + 2*lane    ] = vp[2*n];
                    VSM[w*128 + 32*ch + 8*n + 2*lane + 1] = vp[2*n+1];
                }
            }
        }
        __syncthreads();

        // ---- combine warp pairs -> g_v (atoms 0,1 of this tile) ----
        {
            #pragma unroll
            for (int a = 0; a < 2; ++a)
                g_v[(size_t)(2*bt + a)*Fv + t] =
                    VSM[(2*a)*128 + t] + VSM[(2*a+1)*128 + t];
        }
        __syncthreads();
    }
}

// ---------------- kernel 3: x += dense(ssp(f2out(v)))  [+ next-layer in2f] ----------------
template<int DO_Y>
__global__ __launch_bounds__(256)
void fused_post(const float* __restrict__ W1, const float* __restrict__ B1,
                const float* __restrict__ W2, const float* __restrict__ B2,
                const float* __restrict__ W3, float* __restrict__ x)
{
    extern __shared__ float fsm[];
    float* bufA = fsm;              // [64][128]
    float* bufB = fsm + 64*Fv;      // [64][128]
    const int t = threadIdx.x;
    const int f = t & 127, q = t >> 7;
    const int row0 = blockIdx.x * 64;
    const int r0 = q * 32;

    {   // load v tile
        const float4* src = (const float4*)(g_v + (size_t)row0 * Fv);
        float4* dst = (float4*)bufA;
        #pragma unroll
        for (int i = 0; i < 8; ++i) dst[t + 256*i] = src[t + 256*i];
    }
    __syncthreads();

    float out[32];
    gemm_block(bufA, W1, f, r0, out);
    {
        float b = __ldg(B1 + f);
        #pragma unroll
        for (int r = 0; r < 32; ++r)
            bufB[(r0 + r)*Fv + f] = ssp(out[r] + b);
    }
    __syncthreads();

    gemm_block(bufB, W2, f, r0, out);
    {
        float b = __ldg(B2 + f);
        #pragma unroll
        for (int r = 0; r < 32; ++r) {
            size_t gi = (size_t)(row0 + r0 + r)*Fv + f;
            float xn = x[gi] + out[r] + b;
            x[gi] = xn;
            if (DO_Y) bufA[(r0 + r)*Fv + f] = xn;
        }
    }
    if (DO_Y) {
        __syncthreads();
        gemm_block(bufA, W3, f, r0, out);
        #pragma unroll
        for (int r = 0; r < 32; ++r)
            g_y[(size_t)(row0 + r0 + r)*Fv + f] = __float2bfloat16(out[r]);
    }
}

// ---------------- launcher ----------------
extern "C" void kernel_launch(void* const* d_in, const int* in_sizes, int n_in,
                              void* d_out, int out_size)
{
    const int*   zA   = (const int*)  d_in[0];
    const float* pos  = (const float*)d_in[1];
    const float* cell = (const float*)d_in[2];
    const float* off  = (const float*)d_in[3];
    const int*   nbr  = (const int*)  d_in[4];
    const float* msk  = (const float*)d_in[5];
    const float* emb  = (const float*)d_in[6];
    const float* fw1  = (const float*)d_in[7];
    const float* fb1  = (const float*)d_in[8];
    const float* fw2  = (const float*)d_in[9];
    const float* fb2  = (const float*)d_in[10];
    const float* i2f  = (const float*)d_in[11];
    const float* f2o  = (const float*)d_in[12];
    const float* f2ob = (const float*)d_in[13];
    const float* dw   = (const float*)d_in[14];
    const float* db   = (const float*)d_in[15];
    float* x = (float*)d_out;

    cudaFuncSetAttribute(edge_mma_kernel,
                         cudaFuncAttributeMaxDynamicSharedMemorySize, SMEM_EDGE);
    cudaFuncSetAttribute(fused_post<1>,
                         cudaFuncAttributeMaxDynamicSharedMemorySize, 65536);
    cudaFuncSetAttribute(fused_post<0>,
                         cudaFuncAttributeMaxDynamicSharedMemorySize, 65536);

    init_y_kernel<<<(Bv*Av)/64, 256>>>(zA, pos, cell, off, nbr, emb, i2f, x);
    for (int l = 0; l < Lv; ++l) {
        edge_mma_kernel<<<EDGE_GRID, 128, SMEM_EDGE>>>(
            fw1 + (size_t)l*Gv*Fv, fb1 + (size_t)l*Fv,
            fw2 + (size_t)l*Fv*Fv, fb2 + (size_t)l*Fv, nbr, msk);
        if (l < Lv - 1)
            fused_post<1><<<(Bv*Av)/64, 256, 65536>>>(
                f2o + (size_t)l*Fv*Fv, f2ob + (size_t)l*Fv,
                dw  + (size_t)l*Fv*Fv, db   + (size_t)l*Fv,
                i2f + (size_t)(l+1)*Fv*Fv, x);
        else
            fused_post<0><<<(Bv*Av)/64, 256, 65536>>>(
                f2o + (size_t)l*Fv*Fv, f2ob + (size_t)l*Fv,
                dw  + (size_t)l*Fv*Fv, db   + (size_t)l*Fv,
                (const float*)nullptr, x);
    }
}

// round 7
// speedup vs baseline: 1.1353x; 1.0604x over previous
#include <cuda_runtime.h>
#include <cuda_bf16.h>
#include <cstdint>

#define Bv 8
#define Av 1024
#define NNv 64
#define Gv 25
#define Fv 128
#define Lv 3
#define NBT 4096            // tiles: 2 atoms / 128 edges each
#define EDGE_GRID 304

#define WIDTHc (5.0f/24.0f)
#define COEFFc (-0.5f/(WIDTHc*WIDTHc))
#define LN2c 0.6931471805599453f

// ---- dynamic smem offsets (bytes) for edge kernel (128-thr CTA) ----
#define OFF_YT   0          // bf16 [128 e][136]  stride 272B  (34816 B)
#define OFF_FW2T 34816      // bf16 [128 f][152]  stride 304B  (38912 B)
#define OFF_FB1  73728      // f32 [128]                         (512 B)
#define OFF_VSM  74240      // f32 2 x [4][128]  ping-pong      (4096 B)
#define SMEM_EDGE 78336

// ---------------- scratch ----------------
__device__ __nv_bfloat16 g_y[Bv*Av*Fv];
__device__ float g_v[Bv*Av*Fv];
__device__ float g_r[Bv*Av*NNv];

// ---------------- helpers ----------------
__device__ __forceinline__ float ssp(float x) {
    // softplus(x)-ln2, 1 MUFU: u=e^{-|x|}, ln(1+u) via A&S 4.1.43 poly
    float u = __expf(-fabsf(x));
    float p = u*(0.99949556f + u*(-0.49190896f + u*(0.28947478f
              + u*(-0.13606275f + u*0.03215845f))));
    return fmaxf(x, 0.0f) + p - LN2c;
}
__device__ __forceinline__ uint32_t s2u(const void* p) {
    uint32_t a;
    asm("{ .reg .u64 t; cvta.to.shared.u64 t, %1; cvt.u32.u64 %0, t; }" : "=r"(a) : "l"(p));
    return a;
}
__device__ __forceinline__ uint32_t bf16pk(float lo, float hi) {
    uint32_t r;
    asm("cvt.rn.bf16x2.f32 %0, %1, %2;" : "=r"(r) : "f"(hi), "f"(lo));
    return r;
}
__device__ __forceinline__ float2 bf2f(uint32_t p) {
    float2 r;
    r.x = __uint_as_float(p << 16);
    r.y = __uint_as_float(p & 0xffff0000u);
    return r;
}
__device__ __forceinline__ void mma_bf16(float* d, const uint32_t* a, const uint32_t* b) {
    asm volatile(
        "mma.sync.aligned.m16n8k16.row.col.f32.bf16.bf16.f32 "
        "{%0,%1,%2,%3}, {%4,%5,%6,%7}, {%8,%9}, {%0,%1,%2,%3};"
        : "+f"(d[0]), "+f"(d[1]), "+f"(d[2]), "+f"(d[3])
        : "r"(a[0]), "r"(a[1]), "r"(a[2]), "r"(a[3]), "r"(b[0]), "r"(b[1]));
}
__device__ __forceinline__ void cp16(uint32_t dst, const void* src) {
    asm volatile("cp.async.ca.shared.global [%0], [%1], 16;" :: "r"(dst), "l"(src) : "memory");
}
__device__ __forceinline__ unsigned long long fma2(unsigned long long a,
                                                   unsigned long long b,
                                                   unsigned long long c) {
    unsigned long long d;
    asm("fma.rn.f32x2 %0, %1, %2, %3;" : "=l"(d) : "l"(a), "l"(b), "l"(c));
    return d;
}
__device__ __forceinline__ unsigned long long pack2(float lo, float hi) {
    unsigned long long d;
    asm("mov.b64 %0, {%1, %2};" : "=l"(d) : "f"(lo), "f"(hi));
    return d;
}
__device__ __forceinline__ float hsum2(unsigned long long v) {
    float lo, hi;
    asm("mov.b64 {%0, %1}, %2;" : "=f"(lo), "=f"(hi) : "l"(v));
    return lo + hi;
}

// R-rows x 128x128 GEMM core: thread owns column f, rows [r0, r0+R).
template<int R>
__device__ __forceinline__ void gemm_block(const float* sbuf, const float* __restrict__ W,
                                           int f, int r0, float* out)
{
    unsigned long long acc[R];
    #pragma unroll
    for (int i = 0; i < R; ++i) acc[i] = 0ull;
    const unsigned long long* xs = (const unsigned long long*)sbuf;
    #pragma unroll 2
    for (int kp = 0; kp < 64; ++kp) {
        unsigned long long wp = pack2(__ldg(W + 2*kp*Fv + f), __ldg(W + (2*kp+1)*Fv + f));
        #pragma unroll
        for (int r = 0; r < R; ++r)
            acc[r] = fma2(xs[(r0 + r)*64 + kp], wp, acc[r]);
    }
    #pragma unroll
    for (int r = 0; r < R; ++r) out[r] = hsum2(acc[r]);
}

// ---------------- kernel 0: embedding + distances + y0 GEMM ----------------
__global__ __launch_bounds__(256)
void init_y_kernel(const int* __restrict__ zA, const float* __restrict__ pos,
                   const float* __restrict__ cell, const float* __restrict__ off,
                   const int* __restrict__ nbr, const float* __restrict__ emb,
                   const float* __restrict__ W3, float* __restrict__ x)
{
    __shared__ float bufA[64*Fv];
    __shared__ int zs[64];
    const int t = threadIdx.x;
    const int f = t & 127, q = t >> 7;
    const int row0 = blockIdx.x * 64;
    const int r0 = q * 32;

    if (t < 64) zs[t] = zA[row0 + t];

    for (int i = t; i < 64*NNv; i += 256) {
        int atom = row0 + (i >> 6);
        int e = atom*NNv + (i & 63);
        int b = atom >> 10;
        int nb = nbr[e];
        const float* pi = pos + (size_t)atom*3;
        const float* pj = pos + (size_t)((b<<10) + nb)*3;
        const float* o  = off + (size_t)e*3;
        const float* c  = cell + b*9;
        float dx = pj[0]-pi[0] + o[0]*c[0] + o[1]*c[3] + o[2]*c[6];
        float dy = pj[1]-pi[1] + o[0]*c[1] + o[1]*c[4] + o[2]*c[7];
        float dz = pj[2]-pi[2] + o[0]*c[2] + o[1]*c[5] + o[2]*c[8];
        float d2 = dx*dx + dy*dy + dz*dz;
        g_r[e] = (d2 > 0.0f) ? sqrtf(d2) : 0.0f;
    }
    __syncthreads();

    #pragma unroll
    for (int r = 0; r < 32; ++r) {
        int row = r0 + r;
        float val = emb[(size_t)zs[row]*Fv + f];
        bufA[row*Fv + f] = val;
        x[(size_t)(row0 + row)*Fv + f] = val;
    }
    __syncthreads();

    float out[32];
    gemm_block<32>(bufA, W3, f, r0, out);
    #pragma unroll
    for (int r = 0; r < 32; ++r)
        g_y[(size_t)(row0 + r0 + r)*Fv + f] = __float2bfloat16(out[r]);
}

// ---------------- kernel 2: mma.sync fused filter-net + cfconv ----------------
// 128-thr CTA = 2 atoms = 128 edges; 2 CTAs/SM. ONE __syncthreads per tile:
// r/mask read direct from gmem (L1 broadcast), YT consumption is warp-local
// (cp.async wait + syncwarp), VSM ping-ponged across tiles.
__global__ __launch_bounds__(128)
void edge_mma_kernel(const float* __restrict__ fw1, const float* __restrict__ fb1,
                     const float* __restrict__ fw2, const float* __restrict__ fb2,
                     const int* __restrict__ nbr, const float* __restrict__ msk)
{
    extern __shared__ __align__(16) char sm[];
    __nv_bfloat16* YT   = (__nv_bfloat16*)(sm + OFF_YT);     // [128][136]
    __nv_bfloat16* FW2T = (__nv_bfloat16*)(sm + OFF_FW2T);   // [128][152]
    float* FB1  = (float*)(sm + OFF_FB1);
    float* VSMB = (float*)(sm + OFF_VSM);                    // 2 x [4][128]

    const int t    = threadIdx.x;
    const int w    = t >> 5;
    const int lane = t & 31;
    const int qr   = lane >> 2;   // 0..7
    const int qc   = lane & 3;    // 0..3
    const uint32_t yt_base = s2u(YT);

    // ---- per-layer setup ----
    FB1[t] = fb1[t];
    {   // fw2^T -> smem [f][k], virtual col 128 = fb2, 129..151 = 0
        const int f = t;
        for (int k = 0; k < 128; ++k)
            FW2T[f*152 + k] = __float2bfloat16(fw2[k*Fv + f]);
        FW2T[f*152 + 128] = __float2bfloat16(fb2[f]);
        for (int k = 129; k < 152; ++k) FW2T[f*152 + k] = __float2bfloat16(0.0f);
    }
    // fw1 B-fragments in registers: [kstep s][ntile n][2]
    uint32_t b1f[2][16][2];
    #pragma unroll
    for (int s = 0; s < 2; ++s) {
        #pragma unroll
        for (int n = 0; n < 16; ++n) {
            int g = 2*qc + 16*s;
            int fn = 8*n + qr;
            float w00 = (g   < Gv) ? fw1[(g  )*Fv + fn] : 0.0f;
            float w01 = (g+1 < Gv) ? fw1[(g+1)*Fv + fn] : 0.0f;
            float w10 = (g+8 < Gv) ? fw1[(g+8)*Fv + fn] : 0.0f;
            float w11 = (g+9 < Gv) ? fw1[(g+9)*Fv + fn] : 0.0f;
            b1f[s][n][0] = bf16pk(w00, w01);
            b1f[s][n][1] = bf16pk(w10, w11);
        }
    }
    __syncthreads();

    int par = 0;
    for (int bt = blockIdx.x; bt < NBT; bt += gridDim.x) {
        const int e0 = bt * 128;

        // ---- A: issue y-row stage (bf16) via cp.async; row t is warp-local ----
        {
            int nb = __ldg(nbr + e0 + t);
            int batch = (e0 + t) >> 16;
            const __nv_bfloat16* src = g_y + ((size_t)batch << 17) + (size_t)nb * Fv;
            uint32_t dst = yt_base + (uint32_t)t * 272u;
            #pragma unroll
            for (int j = 0; j < 16; ++j)
                cp16(dst + 16u*j, (const char*)src + 16*j);
            asm volatile("cp.async.commit_group;" ::: "memory");
        }

        // ---- B: GEMM1 -> A2 fragments; r/mask direct from gmem ----
        uint32_t A2[2][9][4];
        float mk[2][2];
        #pragma unroll
        for (int Mt = 0; Mt < 2; ++Mt) {
            const int rg = e0 + 32*w + 16*Mt + qr;
            const float rr0 = __ldg(g_r + rg);
            const float rr1 = __ldg(g_r + rg + 8);
            const float m0  = __ldg(msk + rg);
            const float m1  = __ldg(msk + rg + 8);
            mk[Mt][0] = m0; mk[Mt][1] = m1;

            uint32_t Af[2][4];
            #pragma unroll
            for (int s = 0; s < 2; ++s) {
                const int g = 2*qc + 16*s;
                float d, e00, e01, e02, e03, e10, e11, e12, e13;
                d = rr0 - (g  )*WIDTHc; e00 = (g   < Gv) ? __expf(COEFFc*d*d) : 0.0f;
                d = rr0 - (g+1)*WIDTHc; e01 = (g+1 < Gv) ? __expf(COEFFc*d*d) : 0.0f;
                d = rr0 - (g+8)*WIDTHc; e02 = (g+8 < Gv) ? __expf(COEFFc*d*d) : 0.0f;
                d = rr0 - (g+9)*WIDTHc; e03 = (g+9 < Gv) ? __expf(COEFFc*d*d) : 0.0f;
                d = rr1 - (g  )*WIDTHc; e10 = (g   < Gv) ? __expf(COEFFc*d*d) : 0.0f;
                d = rr1 - (g+1)*WIDTHc; e11 = (g+1 < Gv) ? __expf(COEFFc*d*d) : 0.0f;
                d = rr1 - (g+8)*WIDTHc; e12 = (g+8 < Gv) ? __expf(COEFFc*d*d) : 0.0f;
                d = rr1 - (g+9)*WIDTHc; e13 = (g+9 < Gv) ? __expf(COEFFc*d*d) : 0.0f;
                Af[s][0] = bf16pk(e00, e01);
                Af[s][1] = bf16pk(e10, e11);
                Af[s][2] = bf16pk(e02, e03);
                Af[s][3] = bf16pk(e12, e13);
            }

            #pragma unroll
            for (int s2 = 0; s2 < 8; ++s2) {
                #pragma unroll
                for (int nn = 0; nn < 2; ++nn) {
                    const int n = 2*s2 + nn;
                    float acc[4] = {0.0f, 0.0f, 0.0f, 0.0f};
                    mma_bf16(acc, Af[0], b1f[0][n]);
                    mma_bf16(acc, Af[1], b1f[1][n]);
                    float bA = FB1[8*n + 2*qc];
                    float bB = FB1[8*n + 2*qc + 1];
                    float h0 = ssp(acc[0] + bA) * m0;
                    float h1 = ssp(acc[1] + bB) * m0;
                    float h2 = ssp(acc[2] + bA) * m1;
                    float h3 = ssp(acc[3] + bB) * m1;
                    A2[Mt][s2][2*nn    ] = bf16pk(h0, h1);
                    A2[Mt][s2][2*nn + 1] = bf16pk(h2, h3);
                }
            }
            A2[Mt][8][0] = (qc == 0) ? bf16pk(m0, 0.0f) : 0u;
            A2[Mt][8][1] = (qc == 0) ? bf16pk(m1, 0.0f) : 0u;
            A2[Mt][8][2] = 0u;
            A2[Mt][8][3] = 0u;
        }

        // ---- C: YT ready (warp-local rows only) ----
        asm volatile("cp.async.wait_group 0;" ::: "memory");
        __syncwarp();

        float* VSM = VSMB + par * 512;

        // ---- D/E: GEMM2 + epilogue over 4 f-chunks of 32 ----
        #pragma unroll
        for (int ch = 0; ch < 4; ++ch) {
            float acc2[2][4][4];
            #pragma unroll
            for (int Mt = 0; Mt < 2; ++Mt)
                #pragma unroll
                for (int n = 0; n < 4; ++n)
                    #pragma unroll
                    for (int i = 0; i < 4; ++i) acc2[Mt][n][i] = 0.0f;

            #pragma unroll
            for (int s = 0; s < 9; ++s) {
                #pragma unroll
                for (int n = 0; n < 4; ++n) {
                    int fB = 32*ch + 8*n + qr;
                    int k0 = 16*s + 2*qc;
                    uint32_t bb[2];
                    bb[0] = *(const uint32_t*)(FW2T + fB*152 + k0);
                    bb[1] = *(const uint32_t*)(FW2T + fB*152 + k0 + 8);
                    mma_bf16(acc2[0][n], A2[0][s], bb);
                    mma_bf16(acc2[1][n], A2[1][s], bb);
                }
            }

            float vp[8];
            #pragma unroll
            for (int i = 0; i < 8; ++i) vp[i] = 0.0f;
            #pragma unroll
            for (int Mt = 0; Mt < 2; ++Mt) {
                const int rl = 32*w + 16*Mt + qr;
                #pragma unroll
                for (int n = 0; n < 4; ++n) {
                    int fc = 32*ch + 8*n + 2*qc;
                    uint32_t y0 = *(const uint32_t*)(YT + rl*136 + fc);
                    uint32_t y1 = *(const uint32_t*)(YT + (rl+8)*136 + fc);
                    float2 f0 = bf2f(y0);
                    float2 f1 = bf2f(y1);
                    vp[2*n]   = fmaf(acc2[Mt][n][0], f0.x, fmaf(acc2[Mt][n][2], f1.x, vp[2*n]));
                    vp[2*n+1] = fmaf(acc2[Mt][n][1], f0.y, fmaf(acc2[Mt][n][3], f1.y, vp[2*n+1]));
                }
            }
            #pragma unroll
            for (int i = 0; i < 8; ++i) {
                vp[i] += __shfl_xor_sync(0xffffffffu, vp[i], 4);
                vp[i] += __shfl_xor_sync(0xffffffffu, vp[i], 8);
                vp[i] += __shfl_xor_sync(0xffffffffu, vp[i], 16);
            }
            if (lane < 4) {
                #pragma unroll
                for (int n = 0; n < 4; ++n) {
                    VSM[w*128 + 32*ch + 8*n + 2*lane    ] = vp[2*n];
                    VSM[w*128 + 32*ch + 8*n + 2*lane + 1] = vp[2*n+1];
                }
            }
        }

        // ---- F: single barrier; G: cross-warp combine -> g_v ----
        __syncthreads();
        #pragma unroll
        for (int a = 0; a < 2; ++a)
            g_v[(size_t)(2*bt + a)*Fv + t] =
                VSM[(2*a)*128 + t] + VSM[(2*a+1)*128 + t];
        par ^= 1;
    }
}

// ---------------- kernel 3: x += dense(ssp(f2out(v)))  [+ next-layer in2f] ----------------
template<int DO_Y>
__global__ __launch_bounds__(256)
void fused_post(const float* __restrict__ W1, const float* __restrict__ B1,
                const float* __restrict__ W2, const float* __restrict__ B2,
                const float* __restrict__ W3, float* __restrict__ x)
{
    extern __shared__ float fsm[];
    float* bufA = fsm;              // [32][128]
    float* bufB = fsm + 32*Fv;      // [32][128]
    const int t = threadIdx.x;
    const int f = t & 127, q = t >> 7;
    const int row0 = blockIdx.x * 32;
    const int r0 = q * 16;

    {   // load v tile
        const float4* src = (const float4*)(g_v + (size_t)row0 * Fv);
        float4* dst = (float4*)bufA;
        #pragma unroll
        for (int i = 0; i < 4; ++i) dst[t + 256*i] = src[t + 256*i];
    }
    __syncthreads();

    float out[16];
    gemm_block<16>(bufA, W1, f, r0, out);
    {
        float b = __ldg(B1 + f);
        #pragma unroll
        for (int r = 0; r < 16; ++r)
            bufB[(r0 + r)*Fv + f] = ssp(out[r] + b);
    }
    __syncthreads();

    gemm_block<16>(bufB, W2, f, r0, out);
    {
        float b = __ldg(B2 + f);
        #pragma unroll
        for (int r = 0; r < 16; ++r) {
            size_t gi = (size_t)(row0 + r0 + r)*Fv + f;
            float xn = x[gi] + out[r] + b;
            x[gi] = xn;
            if (DO_Y) bufA[(r0 + r)*Fv + f] = xn;
        }
    }
    if (DO_Y) {
        __syncthreads();
        gemm_block<16>(bufA, W3, f, r0, out);
        #pragma unroll
        for (int r = 0; r < 16; ++r)
            g_y[(size_t)(row0 + r0 + r)*Fv + f] = __float2bfloat16(out[r]);
    }
}

// ---------------- launcher ----------------
extern "C" void kernel_launch(void* const* d_in, const int* in_sizes, int n_in,
                              void* d_out, int out_size)
{
    const int*   zA   = (const int*)  d_in[0];
    const float* pos  = (const float*)d_in[1];
    const float* cell = (const float*)d_in[2];
    const float* off  = (const float*)d_in[3];
    const int*   nbr  = (const int*)  d_in[4];
    const float* msk  = (const float*)d_in[5];
    const float* emb  = (const float*)d_in[6];
    const float* fw1  = (const float*)d_in[7];
    const float* fb1  = (const float*)d_in[8];
    const float* fw2  = (const float*)d_in[9];
    const float* fb2  = (const float*)d_in[10];
    const float* i2f  = (const float*)d_in[11];
    const float* f2o  = (const float*)d_in[12];
    const float* f2ob = (const float*)d_in[13];
    const float* dw   = (const float*)d_in[14];
    const float* db   = (const float*)d_in[15];
    float* x = (float*)d_out;

    cudaFuncSetAttribute(edge_mma_kernel,
                         cudaFuncAttributeMaxDynamicSharedMemorySize, SMEM_EDGE);
    cudaFuncSetAttribute(fused_post<1>,
                         cudaFuncAttributeMaxDynamicSharedMemorySize, 32768);
    cudaFuncSetAttribute(fused_post<0>,
                         cudaFuncAttributeMaxDynamicSharedMemorySize, 32768);

    init_y_kernel<<<(Bv*Av)/64, 256>>>(zA, pos, cell, off, nbr, emb, i2f, x);
    for (int l = 0; l < Lv; ++l) {
        edge_mma_kernel<<<EDGE_GRID, 128, SMEM_EDGE>>>(
            fw1 + (size_t)l*Gv*Fv, fb1 + (size_t)l*Fv,
            fw2 + (size_t)l*Fv*Fv, fb2 + (size_t)l*Fv, nbr, msk);
        if (l < Lv - 1)
            fused_post<1><<<(Bv*Av)/32, 256, 32768>>>(
                f2o + (size_t)l*Fv*Fv, f2ob + (size_t)l*Fv,
                dw  + (size_t)l*Fv*Fv, db   + (size_t)l*Fv,
                i2f + (size_t)(l+1)*Fv*Fv, x);
        else
            fused_post<0><<<(Bv*Av)/32, 256, 32768>>>(
                f2o + (size_t)l*Fv*Fv, f2ob + (size_t)l*Fv,
                dw  + (size_t)l*Fv*Fv, db   + (size_t)l*Fv,
                (const float*)nullptr, x);
    }
}